// round 7
// baseline (speedup 1.0000x reference)
#include <cuda_runtime.h>

#define NN 50000
#define NE 400000
#define NG2 391       // node groups of 128 for the tail scan (391*128 = 50048 >= NN)

// ---------------- scratch (device globals) ----------------
__device__ float g_Z1[NN*256];
__device__ float g_H1[NN*128];
__device__ float g_Z2[NN*128];
__device__ float g_H2[NN*64];
__device__ float g_CONH[NN*64];
__device__ float g_ZM[(size_t)NN*512];
__device__ float g_HM[NN*256];
__device__ float g_AUX[NG2*256];
__device__ float g_el1[NN], g_er1[NN], g_el2[NN], g_er2[NN];
__device__ float g_elm[NN*4], g_erm[NN*4];
__device__ float g_W1[256*64], g_W2[128*128], g_W3[512*64];
// CSR (by dst) for the random graph — shared across all 3 GAT layers
__device__ int g_cnt[NN];
__device__ int g_off[NN+1];
__device__ int g_pos[NN];
__device__ int g_csrc[NE];
__device__ int g_gaux[256];

// ---------------- helpers ----------------
__device__ __forceinline__ unsigned long long pack2(float lo, float hi) {
    unsigned long long r;
    asm("mov.b64 %0, {%1, %2};" : "=l"(r) : "f"(lo), "f"(hi));
    return r;
}
__device__ __forceinline__ void unpack2(float& lo, float& hi, unsigned long long v) {
    asm("mov.b64 {%0, %1}, %2;" : "=f"(lo), "=f"(hi) : "l"(v));
}
__device__ __forceinline__ void ffma2(unsigned long long& d, unsigned long long a, unsigned long long b) {
    asm("fma.rn.f32x2 %0, %1, %2, %0;" : "+l"(d) : "l"(a), "l"(b));
}
__device__ __forceinline__ float lrelu_exp(float v) {
    v = (v >= 0.f) ? v : 0.2f*v;
    return __expf(v);
}

// ---------------- weight pack (concat a;b along rows) ----------------
__global__ void pack_w_kernel(const float* __restrict__ W1a, const float* __restrict__ W1b,
                              const float* __restrict__ W2a, const float* __restrict__ W2b,
                              const float* __restrict__ Wma, const float* __restrict__ Wmb) {
    int i = blockIdx.x*blockDim.x + threadIdx.x;
    if (i < 128*64) { g_W1[i] = W1a[i]; g_W1[128*64 + i] = W1b[i]; }
    if (i < 64*128) { g_W2[i] = W2a[i]; g_W2[64*128 + i] = W2b[i]; }
    if (i < 256*64) { g_W3[i] = Wma[i]; g_W3[256*64 + i] = Wmb[i]; }
}

// ---------------- CSR build ----------------
__global__ void zero_cnt_kernel() {
    int i = blockIdx.x*blockDim.x + threadIdx.x;
    if (i < NN) g_cnt[i] = 0;
}
__global__ void hist_kernel(const int* __restrict__ dst) {
    int e = blockIdx.x*blockDim.x + threadIdx.x;
    if (e < NE) atomicAdd(&g_cnt[dst[e]], 1);
}
__global__ void csr_scan1_kernel() {
    __shared__ int ws[8];
    int g = blockIdx.x, t = threadIdx.x;
    int i = g*256 + t;
    int lane = t & 31, wid = t >> 5;
    int v = (i < NN) ? g_cnt[i] : 0;
    int s = v;
#pragma unroll
    for (int o = 1; o < 32; o <<= 1) {
        int q = __shfl_up_sync(0xffffffffu, s, o);
        if (lane >= o) s += q;
    }
    if (lane == 31) ws[wid] = s;
    __syncthreads();
    if (wid == 0) {
        int w = (lane < 8) ? ws[lane] : 0;
#pragma unroll
        for (int o = 1; o < 8; o <<= 1) {
            int q = __shfl_up_sync(0xffffffffu, w, o);
            if (lane >= o) w += q;
        }
        if (lane < 8) ws[lane] = w;
    }
    __syncthreads();
    int excl = (wid > 0 ? ws[wid-1] : 0) + (s - v);
    if (i < NN) g_off[i] = excl;
    if (t == 0) g_gaux[g] = ws[7];
}
__global__ void csr_scan2_kernel() {
    __shared__ int ws[8];
    int t = threadIdx.x;
    int lane = t & 31, wid = t >> 5;
    int v = (t < 196) ? g_gaux[t] : 0;
    int s = v;
#pragma unroll
    for (int o = 1; o < 32; o <<= 1) {
        int q = __shfl_up_sync(0xffffffffu, s, o);
        if (lane >= o) s += q;
    }
    if (lane == 31) ws[wid] = s;
    __syncthreads();
    if (wid == 0) {
        int w = (lane < 8) ? ws[lane] : 0;
#pragma unroll
        for (int o = 1; o < 8; o <<= 1) {
            int q = __shfl_up_sync(0xffffffffu, w, o);
            if (lane >= o) w += q;
        }
        if (lane < 8) ws[lane] = w;
    }
    __syncthreads();
    int excl = (wid > 0 ? ws[wid-1] : 0) + (s - v);
    if (t < 196) g_gaux[t] = excl;
}
__global__ void csr_apply_kernel() {
    int g = blockIdx.x, t = threadIdx.x;
    int i = g*256 + t;
    if (i < NN) {
        int o = g_off[i] + g_gaux[g];
        g_off[i] = o;
        g_pos[i] = o;
    }
    if (g == 0 && t == 0) g_off[NN] = NE;
}
__global__ void scatter_csr_kernel(const int* __restrict__ src, const int* __restrict__ dst) {
    int e = blockIdx.x*blockDim.x + threadIdx.x;
    if (e >= NE) return;
    int p = atomicAdd(&g_pos[dst[e]], 1);
    g_csrc[p] = src[e];
}

// ---------------- SGEMM, double-buffered, fused attention-dot epilogue ----------------
#define GKC 32
#define GLDS 132

__global__ __launch_bounds__(256, 2)
void gemm_kernel(const float* __restrict__ A, const float* __restrict__ B,
                 float* __restrict__ C, int M, int K, int Ncol,
                 int adimTotal, int hshift, int H,
                 const float* __restrict__ al, const float* __restrict__ ar,
                 float* __restrict__ el, float* __restrict__ er) {
    __shared__ float As[2][GKC][GLDS];
    __shared__ float Bs[2][GKC][GLDS];
    int tid = threadIdx.x;
    int bm = blockIdx.y * 128;
    int bn = blockIdx.x * 128;
    int ty = tid >> 4;
    int tx = tid & 15;
    unsigned long long acc2[8][4];
#pragma unroll
    for (int i = 0; i < 8; i++)
#pragma unroll
        for (int j = 0; j < 4; j++) acc2[i][j] = 0ULL;

    int lrow[4], lk4[4];
#pragma unroll
    for (int ii = 0; ii < 4; ii++) {
        int i = tid + ii*256;
        lrow[ii] = i >> 3;
        lk4[ii]  = (i & 7) << 2;
    }

    float4 va[4], vb[4];
#pragma unroll
    for (int ii = 0; ii < 4; ii++) {
        int gr = bm + lrow[ii];
        va[ii] = (gr < M) ? *(const float4*)(A + (size_t)gr*K + lk4[ii])
                          : make_float4(0.f,0.f,0.f,0.f);
        vb[ii] = *(const float4*)(B + (size_t)(bn + lrow[ii])*K + lk4[ii]);
    }
#pragma unroll
    for (int ii = 0; ii < 4; ii++) {
        As[0][lk4[ii]+0][lrow[ii]] = va[ii].x; As[0][lk4[ii]+1][lrow[ii]] = va[ii].y;
        As[0][lk4[ii]+2][lrow[ii]] = va[ii].z; As[0][lk4[ii]+3][lrow[ii]] = va[ii].w;
        Bs[0][lk4[ii]+0][lrow[ii]] = vb[ii].x; Bs[0][lk4[ii]+1][lrow[ii]] = vb[ii].y;
        Bs[0][lk4[ii]+2][lrow[ii]] = vb[ii].z; Bs[0][lk4[ii]+3][lrow[ii]] = vb[ii].w;
    }
    __syncthreads();

    int ntiles = K / GKC;
    for (int kt = 0; kt < ntiles; kt++) {
        int buf = kt & 1;
        if (kt + 1 < ntiles) {
            int koff = (kt+1)*GKC;
#pragma unroll
            for (int ii = 0; ii < 4; ii++) {
                int gr = bm + lrow[ii];
                va[ii] = (gr < M) ? *(const float4*)(A + (size_t)gr*K + koff + lk4[ii])
                                  : make_float4(0.f,0.f,0.f,0.f);
                vb[ii] = *(const float4*)(B + (size_t)(bn + lrow[ii])*K + koff + lk4[ii]);
            }
        }
#pragma unroll
        for (int k = 0; k < GKC; k++) {
            float a[8], b[8];
            *(float4*)(a)   = *(const float4*)(&As[buf][k][ty<<3]);
            *(float4*)(a+4) = *(const float4*)(&As[buf][k][(ty<<3)+4]);
            *(float4*)(b)   = *(const float4*)(&Bs[buf][k][tx<<3]);
            *(float4*)(b+4) = *(const float4*)(&Bs[buf][k][(tx<<3)+4]);
            unsigned long long a2[8], b2[4];
#pragma unroll
            for (int i = 0; i < 8; i++) a2[i] = pack2(a[i], a[i]);
#pragma unroll
            for (int j = 0; j < 4; j++) b2[j] = pack2(b[2*j], b[2*j+1]);
#pragma unroll
            for (int i = 0; i < 8; i++)
#pragma unroll
                for (int j = 0; j < 4; j++) ffma2(acc2[i][j], a2[i], b2[j]);
        }
        if (kt + 1 < ntiles) {
            int nbuf = buf ^ 1;
            __syncthreads();
#pragma unroll
            for (int ii = 0; ii < 4; ii++) {
                As[nbuf][lk4[ii]+0][lrow[ii]] = va[ii].x; As[nbuf][lk4[ii]+1][lrow[ii]] = va[ii].y;
                As[nbuf][lk4[ii]+2][lrow[ii]] = va[ii].z; As[nbuf][lk4[ii]+3][lrow[ii]] = va[ii].w;
                Bs[nbuf][lk4[ii]+0][lrow[ii]] = vb[ii].x; Bs[nbuf][lk4[ii]+1][lrow[ii]] = vb[ii].y;
                Bs[nbuf][lk4[ii]+2][lrow[ii]] = vb[ii].z; Bs[nbuf][lk4[ii]+3][lrow[ii]] = vb[ii].w;
            }
            __syncthreads();
        }
    }

    bool dact = (el != nullptr) && (bn + (tx<<3)) < adimTotal;
    float alv[8], arv[8];
    if (dact) {
#pragma unroll
        for (int j = 0; j < 8; j++) {
            alv[j] = al[bn + (tx<<3) + j];
            arv[j] = ar[bn + (tx<<3) + j];
        }
    }
    int grp = (el != nullptr) ? (1 << (hshift - 3)) : 0;
    int headg = (el != nullptr) ? ((bn + (tx<<3)) >> hshift) : 0;

#pragma unroll
    for (int i = 0; i < 8; i++) {
        int gr = bm + (ty<<3) + i;
        float c[8];
#pragma unroll
        for (int j = 0; j < 4; j++) unpack2(c[2*j], c[2*j+1], acc2[i][j]);
        if (gr < M) {
            float* Cp = C + (size_t)gr*Ncol + bn + (tx<<3);
            *(float4*)Cp     = make_float4(c[0],c[1],c[2],c[3]);
            *(float4*)(Cp+4) = make_float4(c[4],c[5],c[6],c[7]);
        }
        if (el != nullptr) {
            float sel = 0.f, ser = 0.f;
            if (dact) {
#pragma unroll
                for (int j = 0; j < 8; j++) { sel += c[j]*alv[j]; ser += c[j]*arv[j]; }
            }
            for (int o = grp >> 1; o >= 1; o >>= 1) {
                sel += __shfl_xor_sync(0xffffffffu, sel, o);
                ser += __shfl_xor_sync(0xffffffffu, ser, o);
            }
            if (dact && (tx & (grp-1)) == 0 && gr < M) {
                el[(size_t)gr*H + headg] = sel;
                er[(size_t)gr*H + headg] = ser;
            }
        }
    }
}

// ---------------- CSR aggregation (H=1), 4-wide software-pipelined gather ----------------
template<int D4>
__global__ void agg1_kernel(const float* __restrict__ el, const float* __restrict__ er,
                            const float4* __restrict__ Z4, int ldz4,
                            const float* __restrict__ ba, const float* __restrict__ bb,
                            float4* __restrict__ out4) {
    int t = blockIdx.x*blockDim.x + threadIdx.x;
    int n = t / D4;
    int j = t - n*D4;
    if (n >= NN) return;
    int o0 = g_off[n], o1 = g_off[n+1];
    float ern = er[n];
    float4 acc = make_float4(0.f,0.f,0.f,0.f);
    float den = 0.f;
    for (int p = o0; p < o1; p += 4) {
        int cnt = o1 - p;
        // batch src loads (MLP=4)
        int s0 = g_csrc[p];
        int s1 = (cnt > 1) ? g_csrc[p+1] : s0;
        int s2 = (cnt > 2) ? g_csrc[p+2] : s0;
        int s3 = (cnt > 3) ? g_csrc[p+3] : s0;
        // batch logit loads (MLP=4)
        float l0 = el[s0], l1 = el[s1], l2 = el[s2], l3 = el[s3];
        // batch z-row loads (MLP=4)
        float4 z0 = Z4[(size_t)s0*ldz4 + j];
        float4 z1 = Z4[(size_t)s1*ldz4 + j];
        float4 z2 = Z4[(size_t)s2*ldz4 + j];
        float4 z3 = Z4[(size_t)s3*ldz4 + j];
        float e0 = lrelu_exp(l0 + ern);
        float e1 = (cnt > 1) ? lrelu_exp(l1 + ern) : 0.f;
        float e2 = (cnt > 2) ? lrelu_exp(l2 + ern) : 0.f;
        float e3 = (cnt > 3) ? lrelu_exp(l3 + ern) : 0.f;
        den += (e0 + e1) + (e2 + e3);
        acc.x += e0*z0.x + e1*z1.x + e2*z2.x + e3*z3.x;
        acc.y += e0*z0.y + e1*z1.y + e2*z2.y + e3*z3.y;
        acc.z += e0*z0.z + e1*z1.z + e2*z2.z + e3*z3.z;
        acc.w += e0*z0.w + e1*z1.w + e2*z2.w + e3*z3.w;
    }
    float inv = (o1 > o0) ? 1.f/den : 0.f;
    float4 b1 = ((const float4*)ba)[j];
    float4 b2 = ((const float4*)bb)[j];
    float4 r;
    r.x = acc.x*inv + b1.x + b2.x;
    r.y = acc.y*inv + b1.y + b2.y;
    r.z = acc.z*inv + b1.z + b2.z;
    r.w = acc.w*inv + b1.w + b2.w;
    if (n > 0) {
        float4 zb = Z4[(size_t)(n-1)*ldz4 + D4 + j];
        r.x += zb.x; r.y += zb.y; r.z += zb.z; r.w += zb.w;
    }
    out4[(size_t)n*D4 + j] = make_float4(0.5f*r.x, 0.5f*r.y, 0.5f*r.z, 0.5f*r.w);
}

// ---------------- CSR aggregation (H=4, D=64), 4-wide pipelined ----------------
__global__ void aggmh_kernel(const float* __restrict__ el, const float* __restrict__ er,
                             const float4* __restrict__ Z4,   // ld = 128 float4 (512 f)
                             const float* __restrict__ ba, const float* __restrict__ bb,
                             float4* __restrict__ out4) {     // g_HM as [NN,64] float4
    int w = (blockIdx.x*blockDim.x + threadIdx.x) >> 5;
    int lane = threadIdx.x & 31;
    if (w >= NN) return;
    int n = w;
    int h0 = lane >> 4;
    int h1 = h0 + 2;
    float er0 = er[n*4 + h0], er1 = er[n*4 + h1];
    int o0 = g_off[n], o1 = g_off[n+1];
    float4 acc0 = make_float4(0.f,0.f,0.f,0.f);
    float4 acc1 = make_float4(0.f,0.f,0.f,0.f);
    float den0 = 0.f, den1 = 0.f;
    for (int p = o0; p < o1; p += 4) {
        int cnt = o1 - p;
        int s0 = g_csrc[p];
        int s1 = (cnt > 1) ? g_csrc[p+1] : s0;
        int s2 = (cnt > 2) ? g_csrc[p+2] : s0;
        int s3 = (cnt > 3) ? g_csrc[p+3] : s0;
        // batch logit loads
        float la0 = el[s0*4 + h0], lb0 = el[s0*4 + h1];
        float la1 = el[s1*4 + h0], lb1 = el[s1*4 + h1];
        float la2 = el[s2*4 + h0], lb2 = el[s2*4 + h1];
        float la3 = el[s3*4 + h0], lb3 = el[s3*4 + h1];
        // batch z loads (MLP=8)
        size_t zb0b = (size_t)s0*128, zb1b = (size_t)s1*128,
               zb2b = (size_t)s2*128, zb3b = (size_t)s3*128;
        float4 x0 = Z4[zb0b + lane],      y0 = Z4[zb0b + 32 + lane];
        float4 x1 = Z4[zb1b + lane],      y1 = Z4[zb1b + 32 + lane];
        float4 x2 = Z4[zb2b + lane],      y2 = Z4[zb2b + 32 + lane];
        float4 x3 = Z4[zb3b + lane],      y3 = Z4[zb3b + 32 + lane];
        float ea0 = lrelu_exp(la0 + er0);
        float eb0 = lrelu_exp(lb0 + er1);
        float ea1 = (cnt > 1) ? lrelu_exp(la1 + er0) : 0.f;
        float eb1 = (cnt > 1) ? lrelu_exp(lb1 + er1) : 0.f;
        float ea2 = (cnt > 2) ? lrelu_exp(la2 + er0) : 0.f;
        float eb2 = (cnt > 2) ? lrelu_exp(lb2 + er1) : 0.f;
        float ea3 = (cnt > 3) ? lrelu_exp(la3 + er0) : 0.f;
        float eb3 = (cnt > 3) ? lrelu_exp(lb3 + er1) : 0.f;
        den0 += (ea0 + ea1) + (ea2 + ea3);
        den1 += (eb0 + eb1) + (eb2 + eb3);
        acc0.x += ea0*x0.x + ea1*x1.x + ea2*x2.x + ea3*x3.x;
        acc0.y += ea0*x0.y + ea1*x1.y + ea2*x2.y + ea3*x3.y;
        acc0.z += ea0*x0.z + ea1*x1.z + ea2*x2.z + ea3*x3.z;
        acc0.w += ea0*x0.w + ea1*x1.w + ea2*x2.w + ea3*x3.w;
        acc1.x += eb0*y0.x + eb1*y1.x + eb2*y2.x + eb3*y3.x;
        acc1.y += eb0*y0.y + eb1*y1.y + eb2*y2.y + eb3*y3.y;
        acc1.z += eb0*y0.z + eb1*y1.z + eb2*y2.z + eb3*y3.z;
        acc1.w += eb0*y0.w + eb1*y1.w + eb2*y2.w + eb3*y3.w;
    }
    float i0 = (o1 > o0) ? 1.f/den0 : 0.f;
    float i1 = (o1 > o0) ? 1.f/den1 : 0.f;
    float4 ba0 = ((const float4*)ba)[lane],    bb0 = ((const float4*)bb)[lane];
    float4 ba1 = ((const float4*)ba)[32+lane], bb1 = ((const float4*)bb)[32+lane];
    float4 r0, r1;
    r0.x = acc0.x*i0 + ba0.x + bb0.x; r0.y = acc0.y*i0 + ba0.y + bb0.y;
    r0.z = acc0.z*i0 + ba0.z + bb0.z; r0.w = acc0.w*i0 + ba0.w + bb0.w;
    r1.x = acc1.x*i1 + ba1.x + bb1.x; r1.y = acc1.y*i1 + ba1.y + bb1.y;
    r1.z = acc1.z*i1 + ba1.z + bb1.z; r1.w = acc1.w*i1 + ba1.w + bb1.w;
    if (n > 0) {
        size_t pb = (size_t)(n-1)*128;
        float4 zb0 = Z4[pb + 64 + lane];
        float4 zb1 = Z4[pb + 96 + lane];
        r0.x += zb0.x; r0.y += zb0.y; r0.z += zb0.z; r0.w += zb0.w;
        r1.x += zb1.x; r1.y += zb1.y; r1.z += zb1.z; r1.w += zb1.w;
    }
    out4[(size_t)n*64 + lane]      = make_float4(0.5f*r0.x, 0.5f*r0.y, 0.5f*r0.z, 0.5f*r0.w);
    out4[(size_t)n*64 + 32 + lane] = make_float4(0.5f*r1.x, 0.5f*r1.y, 0.5f*r1.z, 0.5f*r1.w);
}

// ---------------- chain pass (H=1): normalize(h[n-1]-h[n]) ----------------
__global__ void chain_norm_kernel(const float* __restrict__ Hin, float* __restrict__ out) {
    int w = (blockIdx.x*blockDim.x + threadIdx.x) >> 5;
    int lane = threadIdx.x & 31;
    if (w >= NN) return;
    int n = w;
    int base = n*64 + lane*2;
    float d0 = 0.f, d1 = 0.f;
    if (n > 0) {
        d0 = Hin[base - 64]     - Hin[base];
        d1 = Hin[base - 64 + 1] - Hin[base + 1];
    }
    float ss = d0*d0 + d1*d1;
#pragma unroll
    for (int o = 16; o; o >>= 1) ss += __shfl_xor_sync(0xffffffffu, ss, o);
    float inv = 1.f/(sqrtf(ss) + 1e-7f);
    out[base]   = d0*inv;
    out[base+1] = d1*inv;
}

// ---------------- fused tail ----------------
__global__ __launch_bounds__(128)
void dsscan_local_kernel(const float* __restrict__ HM, float* __restrict__ out) {
    int g = blockIdx.x;
    int t = threadIdx.x, wid = t >> 5, lane = t & 31;
    int c = wid*64 + lane*2;
    int start = g*128;
    int end = min(start+128, NN);
    const float2* H2p = (const float2*)HM;
    float2* out2 = (float2*)out;
    int ci = c >> 1;
    float2 prev = (start > 0) ? H2p[(size_t)(start-1)*128 + ci] : make_float2(0.f,0.f);
    float2 cur  = H2p[(size_t)start*128 + ci];
    float rx = 0.f, ry = 0.f;
    for (int n = start; n < end; n++) {
        float2 nxt = (n+1 < end) ? H2p[(size_t)(n+1)*128 + ci] : make_float2(0.f,0.f);
        float d0 = 0.f, d1 = 0.f;
        if (n > 0) { d0 = prev.x - cur.x; d1 = prev.y - cur.y; }
        float ss = d0*d0 + d1*d1;
#pragma unroll
        for (int o = 16; o; o >>= 1) ss += __shfl_xor_sync(0xffffffffu, ss, o);
        float inv = 1.f/(sqrtf(ss) + 1e-7f);
        rx += d0*inv; ry += d1*inv;
        out2[(size_t)n*128 + ci] = make_float2(rx, ry);
        prev = cur; cur = nxt;
    }
    ((float2*)g_AUX)[g*128 + ci] = make_float2(rx, ry);
}
__global__ void aux_scan_kernel() {
    __shared__ float ws[16];
    int c = blockIdx.x;
    int t = threadIdx.x;
    int lane = t & 31, wid = t >> 5;
    float v = (t < NG2) ? g_AUX[t*256 + c] : 0.f;
    float s = v;
#pragma unroll
    for (int o = 1; o < 32; o <<= 1) {
        float q = __shfl_up_sync(0xffffffffu, s, o);
        if (lane >= o) s += q;
    }
    if (lane == 31) ws[wid] = s;
    __syncthreads();
    if (wid == 0) {
        float w = (lane < 16) ? ws[lane] : 0.f;
#pragma unroll
        for (int o = 1; o < 16; o <<= 1) {
            float q = __shfl_up_sync(0xffffffffu, w, o);
            if (lane >= o) w += q;
        }
        if (lane < 16) ws[lane] = w;
    }
    __syncthreads();
    float excl = (wid > 0 ? ws[wid-1] : 0.f) + (s - v);
    if (t < NG2) g_AUX[t*256 + c] = excl;
}
__global__ void add_off_kernel(float* __restrict__ out) {
    int i = blockIdx.x*blockDim.x + threadIdx.x;
    if (i >= NN*64) return;
    int n = i >> 6, c4 = i & 63;
    int g = n >> 7;
    float4 o = ((float4*)out)[i];
    float4 a = ((const float4*)g_AUX)[g*64 + c4];
    o.x += a.x; o.y += a.y; o.z += a.z; o.w += a.w;
    ((float4*)out)[i] = o;
}

// ---------------- host orchestration ----------------
extern "C" void kernel_launch(void* const* d_in, const int* in_sizes, int n_in,
                              void* d_out, int out_size) {
    const float* x    = (const float*)d_in[0];
    const int*   src0 = (const int*)d_in[1];
    const int*   dst0 = (const int*)d_in[2];
    const float* W1a  = (const float*)d_in[5];
    const float* al1a = (const float*)d_in[6];
    const float* ar1a = (const float*)d_in[7];
    const float* b1a  = (const float*)d_in[8];
    const float* W1b  = (const float*)d_in[9];
    const float* b1b  = (const float*)d_in[12];
    const float* W2a  = (const float*)d_in[13];
    const float* al2a = (const float*)d_in[14];
    const float* ar2a = (const float*)d_in[15];
    const float* b2a  = (const float*)d_in[16];
    const float* W2b  = (const float*)d_in[17];
    const float* b2b  = (const float*)d_in[20];
    const float* Wma  = (const float*)d_in[21];
    const float* alma = (const float*)d_in[22];
    const float* arma = (const float*)d_in[23];
    const float* bma  = (const float*)d_in[24];
    const float* Wmb  = (const float*)d_in[25];
    const float* bmb  = (const float*)d_in[28];
    float* out = (float*)d_out;

    float *pZ1,*pH1,*pZ2,*pH2,*pCONH,*pZM,*pHM;
    float *pel1,*per1,*pel2,*per2,*pelm,*perm;
    float *pW1,*pW2,*pW3;
    cudaGetSymbolAddress((void**)&pZ1,  g_Z1);
    cudaGetSymbolAddress((void**)&pH1,  g_H1);
    cudaGetSymbolAddress((void**)&pZ2,  g_Z2);
    cudaGetSymbolAddress((void**)&pH2,  g_H2);
    cudaGetSymbolAddress((void**)&pCONH,g_CONH);
    cudaGetSymbolAddress((void**)&pZM,  g_ZM);
    cudaGetSymbolAddress((void**)&pHM,  g_HM);
    cudaGetSymbolAddress((void**)&pel1, g_el1);
    cudaGetSymbolAddress((void**)&per1, g_er1);
    cudaGetSymbolAddress((void**)&pel2, g_el2);
    cudaGetSymbolAddress((void**)&per2, g_er2);
    cudaGetSymbolAddress((void**)&pelm, g_elm);
    cudaGetSymbolAddress((void**)&perm, g_erm);
    cudaGetSymbolAddress((void**)&pW1,  g_W1);
    cudaGetSymbolAddress((void**)&pW2,  g_W2);
    cudaGetSymbolAddress((void**)&pW3,  g_W3);

    // launch order: ncu capture window (4th launch) hits gemm1
    pack_w_kernel<<<64, 256>>>(W1a, W1b, W2a, W2b, Wma, Wmb);
    zero_cnt_kernel<<<(NN + 255)/256, 256>>>();
    hist_kernel<<<(NE + 255)/256, 256>>>(dst0);

    // ---- layer 1 GEMM (4th launch -> profiled) ----
    gemm_kernel<<<dim3(2, 391), 256>>>(x, pW1, pZ1, NN, 64, 256,
                                       128, 7, 1, al1a, ar1a, pel1, per1);

    // ---- CSR build (independent of GEMM1) ----
    csr_scan1_kernel<<<196, 256>>>();
    csr_scan2_kernel<<<1, 256>>>();
    csr_apply_kernel<<<196, 256>>>();
    scatter_csr_kernel<<<(NE + 255)/256, 256>>>(src0, dst0);

    agg1_kernel<32><<<6250, 256>>>(pel1, per1, (const float4*)pZ1, 64, b1a, b1b, (float4*)pH1);

    // ---- layer 2 ----
    gemm_kernel<<<dim3(1, 391), 256>>>(pH1, pW2, pZ2, NN, 128, 128,
                                       64, 6, 1, al2a, ar2a, pel2, per2);
    agg1_kernel<16><<<3125, 256>>>(pel2, per2, (const float4*)pZ2, 32, b2a, b2b, (float4*)pH2);

    // ---- chain pass -> conh ----
    chain_norm_kernel<<<6250, 256>>>(pH2, pCONH);

    // ---- layer MH ----
    gemm_kernel<<<dim3(4, 391), 256>>>(pCONH, pW3, pZM, NN, 64, 512,
                                       256, 6, 4, alma, arma, pelm, perm);
    aggmh_kernel<<<6250, 256>>>(pelm, perm, (const float4*)pZM, bma, bmb, (float4*)pHM);

    // ---- fused per-head chain pass + cumsum over nodes ----
    dsscan_local_kernel<<<NG2, 128>>>(pHM, out);
    aux_scan_kernel<<<256, 512>>>();
    add_off_kernel<<<(NN*64 + 255)/256, 256>>>(out);
}

// round 8
// speedup vs baseline: 1.1297x; 1.1297x over previous
#include <cuda_runtime.h>

#define NN 50000
#define NE 400000
#define NG2 391       // node groups of 128 for the tail scan

// ---------------- scratch (device globals) ----------------
__device__ float g_Z1[NN*256];
__device__ float g_H1[NN*128];
__device__ float g_Z2[NN*128];
__device__ float g_H2[NN*64];
__device__ float g_CONH[NN*64];
__device__ float g_ZM[(size_t)NN*512];
__device__ float g_HM[NN*256];
__device__ float g_AUX[NG2*256];
__device__ float g_el1[NN], g_er1[NN], g_el2[NN], g_er2[NN];
__device__ float g_elm[NN*4], g_erm[NN*4];
__device__ float g_W1[256*64], g_W2[128*128], g_W3[512*64];
__device__ int g_cnt[NN];
__device__ int g_off[NN+1];
__device__ int g_pos[NN];
__device__ int g_csrc[NE];
__device__ int g_gaux[256];

// ---------------- helpers ----------------
__device__ __forceinline__ float lrelu_exp(float v) {
    v = (v >= 0.f) ? v : 0.2f*v;
    return __expf(v);
}
__device__ __forceinline__ float tf32_rna(float x) {
    unsigned r;
    asm("cvt.rna.tf32.f32 %0, %1;" : "=r"(r) : "f"(x));
    return __uint_as_float(r);
}
__device__ __forceinline__ void mma_tf32(float* c,
                                         unsigned a0, unsigned a1, unsigned a2, unsigned a3,
                                         unsigned b0, unsigned b1) {
    asm volatile("mma.sync.aligned.m16n8k8.row.col.f32.tf32.tf32.f32 "
                 "{%0,%1,%2,%3},{%4,%5,%6,%7},{%8,%9},{%0,%1,%2,%3};"
                 : "+f"(c[0]), "+f"(c[1]), "+f"(c[2]), "+f"(c[3])
                 : "r"(a0), "r"(a1), "r"(a2), "r"(a3), "r"(b0), "r"(b1));
}

// ---------------- weight pack (concat a;b along rows) ----------------
__global__ void pack_w_kernel(const float* __restrict__ W1a, const float* __restrict__ W1b,
                              const float* __restrict__ W2a, const float* __restrict__ W2b,
                              const float* __restrict__ Wma, const float* __restrict__ Wmb) {
    int i = blockIdx.x*blockDim.x + threadIdx.x;
    if (i < 128*64) { g_W1[i] = W1a[i]; g_W1[128*64 + i] = W1b[i]; }
    if (i < 64*128) { g_W2[i] = W2a[i]; g_W2[64*128 + i] = W2b[i]; }
    if (i < 256*64) { g_W3[i] = Wma[i]; g_W3[256*64 + i] = Wmb[i]; }
}

// ---------------- CSR build ----------------
__global__ void zero_cnt_kernel() {
    int i = blockIdx.x*blockDim.x + threadIdx.x;
    if (i < NN) g_cnt[i] = 0;
}
__global__ void hist_kernel(const int* __restrict__ dst) {
    int e = blockIdx.x*blockDim.x + threadIdx.x;
    if (e < NE) atomicAdd(&g_cnt[dst[e]], 1);
}
__global__ void csr_scan1_kernel() {
    __shared__ int ws[8];
    int g = blockIdx.x, t = threadIdx.x;
    int i = g*256 + t;
    int lane = t & 31, wid = t >> 5;
    int v = (i < NN) ? g_cnt[i] : 0;
    int s = v;
#pragma unroll
    for (int o = 1; o < 32; o <<= 1) {
        int q = __shfl_up_sync(0xffffffffu, s, o);
        if (lane >= o) s += q;
    }
    if (lane == 31) ws[wid] = s;
    __syncthreads();
    if (wid == 0) {
        int w = (lane < 8) ? ws[lane] : 0;
#pragma unroll
        for (int o = 1; o < 8; o <<= 1) {
            int q = __shfl_up_sync(0xffffffffu, w, o);
            if (lane >= o) w += q;
        }
        if (lane < 8) ws[lane] = w;
    }
    __syncthreads();
    int excl = (wid > 0 ? ws[wid-1] : 0) + (s - v);
    if (i < NN) g_off[i] = excl;
    if (t == 0) g_gaux[g] = ws[7];
}
__global__ void csr_scan2_kernel() {
    __shared__ int ws[8];
    int t = threadIdx.x;
    int lane = t & 31, wid = t >> 5;
    int v = (t < 196) ? g_gaux[t] : 0;
    int s = v;
#pragma unroll
    for (int o = 1; o < 32; o <<= 1) {
        int q = __shfl_up_sync(0xffffffffu, s, o);
        if (lane >= o) s += q;
    }
    if (lane == 31) ws[wid] = s;
    __syncthreads();
    if (wid == 0) {
        int w = (lane < 8) ? ws[lane] : 0;
#pragma unroll
        for (int o = 1; o < 8; o <<= 1) {
            int q = __shfl_up_sync(0xffffffffu, w, o);
            if (lane >= o) w += q;
        }
        if (lane < 8) ws[lane] = w;
    }
    __syncthreads();
    int excl = (wid > 0 ? ws[wid-1] : 0) + (s - v);
    if (t < 196) g_gaux[t] = excl;
}
__global__ void csr_apply_kernel() {
    int g = blockIdx.x, t = threadIdx.x;
    int i = g*256 + t;
    if (i < NN) {
        int o = g_off[i] + g_gaux[g];
        g_off[i] = o;
        g_pos[i] = o;
    }
    if (g == 0 && t == 0) g_off[NN] = NE;
}
__global__ void scatter_csr_kernel(const int* __restrict__ src, const int* __restrict__ dst) {
    int e = blockIdx.x*blockDim.x + threadIdx.x;
    if (e >= NE) return;
    int p = atomicAdd(&g_pos[dst[e]], 1);
    g_csrc[p] = src[e];
}

// ---------------- 3xTF32 tensor-core GEMM with fused attention-dot epilogue ----------------
// C[M,Ncol] = A[M,K] * B[Ncol,K]^T  via mma.sync.m16n8k8.tf32, error-compensated (hi/lo split).
// Block tile 128x128, 8 warps (warpM = w&3 -> 32 rows, warpN = w>>2 -> 64 cols).
#define GKC 16
#define GLDS 132

__global__ __launch_bounds__(256, 2)
void gemm_kernel(const float* __restrict__ A, const float* __restrict__ B,
                 float* __restrict__ C, int M, int K, int Ncol,
                 int adimTotal, int hshift, int H,
                 const float* __restrict__ al, const float* __restrict__ ar,
                 float* __restrict__ el, float* __restrict__ er) {
    __shared__ float Ahi[GKC][GLDS];
    __shared__ float Alo[GKC][GLDS];
    __shared__ float Bhi[GKC][GLDS];
    __shared__ float Blo[GKC][GLDS];
    __shared__ float epiel[2][128];
    __shared__ float epier[2][128];

    int tid = threadIdx.x;
    int bm = blockIdx.y * 128;
    int bn = blockIdx.x * 128;
    int w = tid >> 5;
    int lane = tid & 31;
    int warpM = w & 3;        // 4 M-slices of 32 rows
    int warpN = w >> 2;       // 2 N-slices of 64 cols
    int g  = lane >> 2;       // groupID 0..7
    int tg = lane & 3;        // thread-in-group 0..3

    float acc[2][8][4];
#pragma unroll
    for (int mt = 0; mt < 2; mt++)
#pragma unroll
        for (int nt = 0; nt < 8; nt++)
#pragma unroll
            for (int q = 0; q < 4; q++) acc[mt][nt][q] = 0.f;

    int ntiles = K / GKC;
    for (int kt = 0; kt < ntiles; kt++) {
        int koff = kt * GKC;
        // fill smem: hi/lo tf32 split, k-major layout [k][row]
#pragma unroll
        for (int ii = 0; ii < 2; ii++) {
            int i = tid + ii*256;           // 0..511, 4 float4 per row
            int row = i >> 2;
            int k4  = (i & 3) << 2;
            float4 va = make_float4(0.f,0.f,0.f,0.f);
            int gr = bm + row;
            if (gr < M) va = *(const float4*)(A + (size_t)gr*K + koff + k4);
            float4 vb = *(const float4*)(B + (size_t)(bn + row)*K + koff + k4);
            float h, l;
            h = tf32_rna(va.x); l = tf32_rna(va.x - h); Ahi[k4+0][row] = h; Alo[k4+0][row] = l;
            h = tf32_rna(va.y); l = tf32_rna(va.y - h); Ahi[k4+1][row] = h; Alo[k4+1][row] = l;
            h = tf32_rna(va.z); l = tf32_rna(va.z - h); Ahi[k4+2][row] = h; Alo[k4+2][row] = l;
            h = tf32_rna(va.w); l = tf32_rna(va.w - h); Ahi[k4+3][row] = h; Alo[k4+3][row] = l;
            h = tf32_rna(vb.x); l = tf32_rna(vb.x - h); Bhi[k4+0][row] = h; Blo[k4+0][row] = l;
            h = tf32_rna(vb.y); l = tf32_rna(vb.y - h); Bhi[k4+1][row] = h; Blo[k4+1][row] = l;
            h = tf32_rna(vb.z); l = tf32_rna(vb.z - h); Bhi[k4+2][row] = h; Blo[k4+2][row] = l;
            h = tf32_rna(vb.w); l = tf32_rna(vb.w - h); Bhi[k4+3][row] = h; Blo[k4+3][row] = l;
        }
        __syncthreads();

#pragma unroll
        for (int k8 = 0; k8 < GKC/8; k8++) {
            int kb = k8*8;
            unsigned ah[2][4], alr[2][4];
#pragma unroll
            for (int mt = 0; mt < 2; mt++) {
                int rb = warpM*32 + mt*16;
                ah[mt][0] = __float_as_uint(Ahi[kb+tg  ][rb+g  ]);
                ah[mt][1] = __float_as_uint(Ahi[kb+tg  ][rb+g+8]);
                ah[mt][2] = __float_as_uint(Ahi[kb+tg+4][rb+g  ]);
                ah[mt][3] = __float_as_uint(Ahi[kb+tg+4][rb+g+8]);
                alr[mt][0] = __float_as_uint(Alo[kb+tg  ][rb+g  ]);
                alr[mt][1] = __float_as_uint(Alo[kb+tg  ][rb+g+8]);
                alr[mt][2] = __float_as_uint(Alo[kb+tg+4][rb+g  ]);
                alr[mt][3] = __float_as_uint(Alo[kb+tg+4][rb+g+8]);
            }
#pragma unroll
            for (int nt = 0; nt < 8; nt++) {
                int nb = warpN*64 + nt*8;
                unsigned bh0 = __float_as_uint(Bhi[kb+tg  ][nb+g]);
                unsigned bh1 = __float_as_uint(Bhi[kb+tg+4][nb+g]);
                unsigned bl0 = __float_as_uint(Blo[kb+tg  ][nb+g]);
                unsigned bl1 = __float_as_uint(Blo[kb+tg+4][nb+g]);
#pragma unroll
                for (int mt = 0; mt < 2; mt++) {
                    mma_tf32(acc[mt][nt], ah[mt][0], ah[mt][1], ah[mt][2], ah[mt][3], bh0, bh1);
                    mma_tf32(acc[mt][nt], ah[mt][0], ah[mt][1], ah[mt][2], ah[mt][3], bl0, bl1);
                    mma_tf32(acc[mt][nt], alr[mt][0], alr[mt][1], alr[mt][2], alr[mt][3], bh0, bh1);
                }
            }
        }
        __syncthreads();
    }

    // ---- C store + fused el/er partials ----
    bool awarp = (el != nullptr) && (bn + warpN*64) < adimTotal;
    float pel[2][2] = {{0.f,0.f},{0.f,0.f}};
    float per_[2][2] = {{0.f,0.f},{0.f,0.f}};
#pragma unroll
    for (int mt = 0; mt < 2; mt++) {
        int r0 = bm + warpM*32 + mt*16 + g;
#pragma unroll
        for (int nt = 0; nt < 8; nt++) {
            int gc = bn + warpN*64 + nt*8 + tg*2;
            float c0 = acc[mt][nt][0], c1 = acc[mt][nt][1];
            float c2 = acc[mt][nt][2], c3 = acc[mt][nt][3];
            if (r0 < M)     *(float2*)(C + (size_t)r0*Ncol + gc)     = make_float2(c0, c1);
            if (r0+8 < M)   *(float2*)(C + (size_t)(r0+8)*Ncol + gc) = make_float2(c2, c3);
            if (awarp) {
                float w0 = al[gc], w1 = al[gc+1];
                float u0 = ar[gc], u1 = ar[gc+1];
                pel[mt][0] += c0*w0 + c1*w1;
                pel[mt][1] += c2*w0 + c3*w1;
                per_[mt][0] += c0*u0 + c1*u1;
                per_[mt][1] += c2*u0 + c3*u1;
            }
        }
    }
    if (el != nullptr) {
#pragma unroll
        for (int mt = 0; mt < 2; mt++)
#pragma unroll
            for (int rp = 0; rp < 2; rp++) {
#pragma unroll
                for (int o = 1; o <= 2; o <<= 1) {
                    pel[mt][rp]  += __shfl_xor_sync(0xffffffffu, pel[mt][rp],  o);
                    per_[mt][rp] += __shfl_xor_sync(0xffffffffu, per_[mt][rp], o);
                }
                if (tg == 0) {
                    int row = warpM*32 + mt*16 + g + rp*8;
                    epiel[warpN][row] = pel[mt][rp];
                    epier[warpN][row] = per_[mt][rp];
                }
            }
        __syncthreads();
        if (tid < 128) {
            int row = tid;
            int gr = bm + row;
            if (gr < M) {
                int span = 1 << hshift;
                if (span == 128) {
                    if (bn < adimTotal) {
                        el[gr] = epiel[0][row] + epiel[1][row];
                        er[gr] = epier[0][row] + epier[1][row];
                    }
                } else {  // span == 64
#pragma unroll
                    for (int wn = 0; wn < 2; wn++) {
                        int cb = bn + wn*64;
                        if (cb < adimTotal) {
                            int h = cb >> hshift;
                            el[(size_t)gr*H + h] = epiel[wn][row];
                            er[(size_t)gr*H + h] = epier[wn][row];
                        }
                    }
                }
            }
        }
    }
}

// ---------------- CSR aggregation (H=1) with fused finalize ----------------
template<int D4>
__global__ void agg1_kernel(const float* __restrict__ el, const float* __restrict__ er,
                            const float4* __restrict__ Z4, int ldz4,
                            const float* __restrict__ ba, const float* __restrict__ bb,
                            float4* __restrict__ out4) {
    int t = blockIdx.x*blockDim.x + threadIdx.x;
    int n = t / D4;
    int j = t - n*D4;
    if (n >= NN) return;
    int o0 = g_off[n], o1 = g_off[n+1];
    float ern = er[n];
    float4 acc = make_float4(0.f,0.f,0.f,0.f);
    float den = 0.f;
    for (int p = o0; p < o1; p++) {
        int s = g_csrc[p];
        float ee = lrelu_exp(el[s] + ern);
        den += ee;
        float4 z = Z4[(size_t)s*ldz4 + j];
        acc.x += ee*z.x; acc.y += ee*z.y; acc.z += ee*z.z; acc.w += ee*z.w;
    }
    float inv = (o1 > o0) ? 1.f/den : 0.f;
    float4 b1 = ((const float4*)ba)[j];
    float4 b2 = ((const float4*)bb)[j];
    float4 r;
    r.x = acc.x*inv + b1.x + b2.x;
    r.y = acc.y*inv + b1.y + b2.y;
    r.z = acc.z*inv + b1.z + b2.z;
    r.w = acc.w*inv + b1.w + b2.w;
    if (n > 0) {
        float4 zb = Z4[(size_t)(n-1)*ldz4 + D4 + j];
        r.x += zb.x; r.y += zb.y; r.z += zb.z; r.w += zb.w;
    }
    out4[(size_t)n*D4 + j] = make_float4(0.5f*r.x, 0.5f*r.y, 0.5f*r.z, 0.5f*r.w);
}

// ---------------- CSR aggregation (H=4, D=64) with fused finalize ----------------
__global__ void aggmh_kernel(const float* __restrict__ el, const float* __restrict__ er,
                             const float4* __restrict__ Z4,
                             const float* __restrict__ ba, const float* __restrict__ bb,
                             float4* __restrict__ out4) {
    int w = (blockIdx.x*blockDim.x + threadIdx.x) >> 5;
    int lane = threadIdx.x & 31;
    if (w >= NN) return;
    int n = w;
    int h0 = lane >> 4;
    int h1 = h0 + 2;
    float er0 = er[n*4 + h0], er1 = er[n*4 + h1];
    int o0 = g_off[n], o1 = g_off[n+1];
    float4 acc0 = make_float4(0.f,0.f,0.f,0.f);
    float4 acc1 = make_float4(0.f,0.f,0.f,0.f);
    float den0 = 0.f, den1 = 0.f;
    for (int p = o0; p < o1; p++) {
        int s = g_csrc[p];
        float e0 = lrelu_exp(el[s*4 + h0] + er0);
        float e1 = lrelu_exp(el[s*4 + h1] + er1);
        den0 += e0; den1 += e1;
        size_t zb = (size_t)s*128;
        float4 z0 = Z4[zb + lane];
        float4 z1 = Z4[zb + 32 + lane];
        acc0.x += e0*z0.x; acc0.y += e0*z0.y; acc0.z += e0*z0.z; acc0.w += e0*z0.w;
        acc1.x += e1*z1.x; acc1.y += e1*z1.y; acc1.z += e1*z1.z; acc1.w += e1*z1.w;
    }
    float i0 = (o1 > o0) ? 1.f/den0 : 0.f;
    float i1 = (o1 > o0) ? 1.f/den1 : 0.f;
    float4 ba0 = ((const float4*)ba)[lane],    bb0 = ((const float4*)bb)[lane];
    float4 ba1 = ((const float4*)ba)[32+lane], bb1 = ((const float4*)bb)[32+lane];
    float4 r0, r1;
    r0.x = acc0.x*i0 + ba0.x + bb0.x; r0.y = acc0.y*i0 + ba0.y + bb0.y;
    r0.z = acc0.z*i0 + ba0.z + bb0.z; r0.w = acc0.w*i0 + ba0.w + bb0.w;
    r1.x = acc1.x*i1 + ba1.x + bb1.x; r1.y = acc1.y*i1 + ba1.y + bb1.y;
    r1.z = acc1.z*i1 + ba1.z + bb1.z; r1.w = acc1.w*i1 + ba1.w + bb1.w;
    if (n > 0) {
        size_t pb = (size_t)(n-1)*128;
        float4 zb0 = Z4[pb + 64 + lane];
        float4 zb1 = Z4[pb + 96 + lane];
        r0.x += zb0.x; r0.y += zb0.y; r0.z += zb0.z; r0.w += zb0.w;
        r1.x += zb1.x; r1.y += zb1.y; r1.z += zb1.z; r1.w += zb1.w;
    }
    out4[(size_t)n*64 + lane]      = make_float4(0.5f*r0.x, 0.5f*r0.y, 0.5f*r0.z, 0.5f*r0.w);
    out4[(size_t)n*64 + 32 + lane] = make_float4(0.5f*r1.x, 0.5f*r1.y, 0.5f*r1.z, 0.5f*r1.w);
}

// ---------------- chain pass (H=1): normalize(h[n-1]-h[n]) ----------------
__global__ void chain_norm_kernel(const float* __restrict__ Hin, float* __restrict__ out) {
    int w = (blockIdx.x*blockDim.x + threadIdx.x) >> 5;
    int lane = threadIdx.x & 31;
    if (w >= NN) return;
    int n = w;
    int base = n*64 + lane*2;
    float d0 = 0.f, d1 = 0.f;
    if (n > 0) {
        d0 = Hin[base - 64]     - Hin[base];
        d1 = Hin[base - 64 + 1] - Hin[base + 1];
    }
    float ss = d0*d0 + d1*d1;
#pragma unroll
    for (int o = 16; o; o >>= 1) ss += __shfl_xor_sync(0xffffffffu, ss, o);
    float inv = 1.f/(sqrtf(ss) + 1e-7f);
    out[base]   = d0*inv;
    out[base+1] = d1*inv;
}

// ---------------- fused tail ----------------
__global__ __launch_bounds__(128)
void dsscan_local_kernel(const float* __restrict__ HM, float* __restrict__ out) {
    int g = blockIdx.x;
    int t = threadIdx.x, wid = t >> 5, lane = t & 31;
    int c = wid*64 + lane*2;
    int start = g*128;
    int end = min(start+128, NN);
    const float2* H2p = (const float2*)HM;
    float2* out2 = (float2*)out;
    int ci = c >> 1;
    float2 prev = (start > 0) ? H2p[(size_t)(start-1)*128 + ci] : make_float2(0.f,0.f);
    float2 cur  = H2p[(size_t)start*128 + ci];
    float rx = 0.f, ry = 0.f;
    for (int n = start; n < end; n++) {
        float2 nxt = (n+1 < end) ? H2p[(size_t)(n+1)*128 + ci] : make_float2(0.f,0.f);
        float d0 = 0.f, d1 = 0.f;
        if (n > 0) { d0 = prev.x - cur.x; d1 = prev.y - cur.y; }
        float ss = d0*d0 + d1*d1;
#pragma unroll
        for (int o = 16; o; o >>= 1) ss += __shfl_xor_sync(0xffffffffu, ss, o);
        float inv = 1.f/(sqrtf(ss) + 1e-7f);
        rx += d0*inv; ry += d1*inv;
        out2[(size_t)n*128 + ci] = make_float2(rx, ry);
        prev = cur; cur = nxt;
    }
    ((float2*)g_AUX)[g*128 + ci] = make_float2(rx, ry);
}
__global__ void aux_scan_kernel() {
    __shared__ float ws[16];
    int c = blockIdx.x;
    int t = threadIdx.x;
    int lane = t & 31, wid = t >> 5;
    float v = (t < NG2) ? g_AUX[t*256 + c] : 0.f;
    float s = v;
#pragma unroll
    for (int o = 1; o < 32; o <<= 1) {
        float q = __shfl_up_sync(0xffffffffu, s, o);
        if (lane >= o) s += q;
    }
    if (lane == 31) ws[wid] = s;
    __syncthreads();
    if (wid == 0) {
        float w = (lane < 16) ? ws[lane] : 0.f;
#pragma unroll
        for (int o = 1; o < 16; o <<= 1) {
            float q = __shfl_up_sync(0xffffffffu, w, o);
            if (lane >= o) w += q;
        }
        if (lane < 16) ws[lane] = w;
    }
    __syncthreads();
    float excl = (wid > 0 ? ws[wid-1] : 0.f) + (s - v);
    if (t < NG2) g_AUX[t*256 + c] = excl;
}
__global__ void add_off_kernel(float* __restrict__ out) {
    int i = blockIdx.x*blockDim.x + threadIdx.x;
    if (i >= NN*64) return;
    int n = i >> 6, c4 = i & 63;
    int g = n >> 7;
    float4 o = ((float4*)out)[i];
    float4 a = ((const float4*)g_AUX)[g*64 + c4];
    o.x += a.x; o.y += a.y; o.z += a.z; o.w += a.w;
    ((float4*)out)[i] = o;
}

// ---------------- host orchestration ----------------
extern "C" void kernel_launch(void* const* d_in, const int* in_sizes, int n_in,
                              void* d_out, int out_size) {
    const float* x    = (const float*)d_in[0];
    const int*   src0 = (const int*)d_in[1];
    const int*   dst0 = (const int*)d_in[2];
    const float* W1a  = (const float*)d_in[5];
    const float* al1a = (const float*)d_in[6];
    const float* ar1a = (const float*)d_in[7];
    const float* b1a  = (const float*)d_in[8];
    const float* W1b  = (const float*)d_in[9];
    const float* b1b  = (const float*)d_in[12];
    const float* W2a  = (const float*)d_in[13];
    const float* al2a = (const float*)d_in[14];
    const float* ar2a = (const float*)d_in[15];
    const float* b2a  = (const float*)d_in[16];
    const float* W2b  = (const float*)d_in[17];
    const float* b2b  = (const float*)d_in[20];
    const float* Wma  = (const float*)d_in[21];
    const float* alma = (const float*)d_in[22];
    const float* arma = (const float*)d_in[23];
    const float* bma  = (const float*)d_in[24];
    const float* Wmb  = (const float*)d_in[25];
    const float* bmb  = (const float*)d_in[28];
    float* out = (float*)d_out;

    float *pZ1,*pH1,*pZ2,*pH2,*pCONH,*pZM,*pHM;
    float *pel1,*per1,*pel2,*per2,*pelm,*perm;
    float *pW1,*pW2,*pW3;
    cudaGetSymbolAddress((void**)&pZ1,  g_Z1);
    cudaGetSymbolAddress((void**)&pH1,  g_H1);
    cudaGetSymbolAddress((void**)&pZ2,  g_Z2);
    cudaGetSymbolAddress((void**)&pH2,  g_H2);
    cudaGetSymbolAddress((void**)&pCONH,g_CONH);
    cudaGetSymbolAddress((void**)&pZM,  g_ZM);
    cudaGetSymbolAddress((void**)&pHM,  g_HM);
    cudaGetSymbolAddress((void**)&pel1, g_el1);
    cudaGetSymbolAddress((void**)&per1, g_er1);
    cudaGetSymbolAddress((void**)&pel2, g_el2);
    cudaGetSymbolAddress((void**)&per2, g_er2);
    cudaGetSymbolAddress((void**)&pelm, g_elm);
    cudaGetSymbolAddress((void**)&perm, g_erm);
    cudaGetSymbolAddress((void**)&pW1,  g_W1);
    cudaGetSymbolAddress((void**)&pW2,  g_W2);
    cudaGetSymbolAddress((void**)&pW3,  g_W3);

    // launch order: ncu capture window (4th launch) hits gemm1
    pack_w_kernel<<<64, 256>>>(W1a, W1b, W2a, W2b, Wma, Wmb);
    zero_cnt_kernel<<<(NN + 255)/256, 256>>>();
    hist_kernel<<<(NE + 255)/256, 256>>>(dst0);

    // ---- layer 1 GEMM (4th launch -> profiled) ----
    gemm_kernel<<<dim3(2, 391), 256>>>(x, pW1, pZ1, NN, 64, 256,
                                       128, 7, 1, al1a, ar1a, pel1, per1);

    // ---- CSR build (independent of GEMM1) ----
    csr_scan1_kernel<<<196, 256>>>();
    csr_scan2_kernel<<<1, 256>>>();
    csr_apply_kernel<<<196, 256>>>();
    scatter_csr_kernel<<<(NE + 255)/256, 256>>>(src0, dst0);

    agg1_kernel<32><<<6250, 256>>>(pel1, per1, (const float4*)pZ1, 64, b1a, b1b, (float4*)pH1);

    // ---- layer 2 ----
    gemm_kernel<<<dim3(1, 391), 256>>>(pH1, pW2, pZ2, NN, 128, 128,
                                       64, 6, 1, al2a, ar2a, pel2, per2);
    agg1_kernel<16><<<3125, 256>>>(pel2, per2, (const float4*)pZ2, 32, b2a, b2b, (float4*)pH2);

    // ---- chain pass -> conh ----
    chain_norm_kernel<<<6250, 256>>>(pH2, pCONH);

    // ---- layer MH ----
    gemm_kernel<<<dim3(4, 391), 256>>>(pCONH, pW3, pZM, NN, 64, 512,
                                       256, 6, 4, alma, arma, pelm, perm);
    aggmh_kernel<<<6250, 256>>>(pelm, perm, (const float4*)pZM, bma, bmb, (float4*)pHM);

    // ---- fused per-head chain pass + cumsum over nodes ----
    dsscan_local_kernel<<<NG2, 128>>>(pHM, out);
    aux_scan_kernel<<<256, 512>>>();
    add_off_kernel<<<(NN*64 + 255)/256, 256>>>(out);
}